// round 3
// baseline (speedup 1.0000x reference)
#include <cuda_runtime.h>
#include <cstdint>

#define N_NODES 50000
#define N_EDGES 800000
#define IN_F    256
#define HEADS   4
#define OUTF    64
#define HF      256   // HEADS*OUTF
#define SLOPE   0.2f

// ---------------- scratch (device globals; no allocation allowed) ----------
__device__ __align__(16) float g_h[N_NODES * HF];        // 51.2 MB projected features
__device__ __align__(16) float g_asrc[N_NODES * HEADS];  // per-node att halves
__device__ __align__(16) float g_adst[N_NODES * HEADS];
__device__ __align__(16) float g_denom[N_NODES * HEADS]; // softmax denominators
__device__ __align__(16) float g_exself[N_NODES * HEADS];// self-loop numerators
__device__ __align__(16) float g_ex[N_EDGES * HEADS];    // per-edge numerators (12.8 MB)

__device__ __forceinline__ float leaky(float v) {
    return v > 0.0f ? v : SLOPE * v;
}

__device__ __forceinline__ void red_add_v4(float* p, float a, float b, float c, float d) {
    asm volatile("red.global.add.v4.f32 [%0], {%1,%2,%3,%4};"
                 :: "l"(p), "f"(a), "f"(b), "f"(c), "f"(d) : "memory");
}

__device__ __forceinline__ float tf32r(float x) {
    uint32_t u;
    asm("cvt.rna.tf32.f32 %0, %1;" : "=r"(u) : "f"(x));
    return __uint_as_float(u);
}

#define MMA8(c, a0, a1, a2, a3, b0, b1)                                        \
    asm volatile("mma.sync.aligned.m16n8k8.row.col.f32.tf32.tf32.f32 "         \
                 "{%0,%1,%2,%3}, {%4,%5,%6,%7}, {%8,%9}, {%0,%1,%2,%3};"       \
                 : "+f"(c[0]), "+f"(c[1]), "+f"(c[2]), "+f"(c[3])              \
                 : "r"(a0), "r"(a1), "r"(a2), "r"(a3), "r"(b0), "r"(b1))

// ---------------------------------------------------------------------------
// K1: h = x @ W  on tensor cores (3xTF32 split, ~fp32 accuracy).
//     Block tile 128x64 (BN=64 == one head), BK=16. 8 warps, warp tile 16x64.
//     Epilogue fuses a_src/a_dst head-dot AND self-loop exp / denom init.
// ---------------------------------------------------------------------------
#define BK 16

__global__ __launch_bounds__(256) void k_gemm_tc(const float* __restrict__ x,
                                                 const float* __restrict__ W,
                                                 const float* __restrict__ att_s,
                                                 const float* __restrict__ att_d)
{
    __shared__ float AsH[128][20], AsL[128][20];   // pad 20: frag banks (4g+t) conflict-free
    __shared__ float BsH[BK][72],  BsL[BK][72];    // pad 72: frag banks (8t+g) conflict-free

    const int head = blockIdx.y;
    const int r0 = blockIdx.x * 128;
    const int c0 = head * OUTF;
    const int tid = threadIdx.x;
    const int lane = tid & 31;
    const int warp = tid >> 5;
    const int g = lane >> 2;      // groupID (0..7)
    const int t = lane & 3;       // tid-in-group (0..3)

    float acc[8][4];              // 8 n8-tiles x {c0,c1,c2,c3}
#pragma unroll
    for (int i = 0; i < 8; i++)
#pragma unroll
        for (int j = 0; j < 4; j++) acc[i][j] = 0.0f;

    for (int k0 = 0; k0 < IN_F; k0 += BK) {
        // A tile 128x16: 512 float4, 2 per thread; split into hi/lo tf32
#pragma unroll
        for (int i = 0; i < 2; i++) {
            int q = tid + i * 256;
            int row = q >> 2;
            int cc = (q & 3) << 2;
            int r = r0 + row;
            float4 v = make_float4(0.f, 0.f, 0.f, 0.f);
            if (r < N_NODES) v = *(const float4*)&x[r * IN_F + k0 + cc];
            float h0 = tf32r(v.x), h1 = tf32r(v.y), h2 = tf32r(v.z), h3 = tf32r(v.w);
            AsH[row][cc + 0] = h0; AsL[row][cc + 0] = tf32r(v.x - h0);
            AsH[row][cc + 1] = h1; AsL[row][cc + 1] = tf32r(v.y - h1);
            AsH[row][cc + 2] = h2; AsL[row][cc + 2] = tf32r(v.z - h2);
            AsH[row][cc + 3] = h3; AsL[row][cc + 3] = tf32r(v.w - h3);
        }
        // B tile 16x64: 256 float4, 1 per thread
        {
            int row = tid >> 4;
            int cc = (tid & 15) << 2;
            float4 v = *(const float4*)&W[(k0 + row) * HF + c0 + cc];
            float h0 = tf32r(v.x), h1 = tf32r(v.y), h2 = tf32r(v.z), h3 = tf32r(v.w);
            BsH[row][cc + 0] = h0; BsL[row][cc + 0] = tf32r(v.x - h0);
            BsH[row][cc + 1] = h1; BsL[row][cc + 1] = tf32r(v.y - h1);
            BsH[row][cc + 2] = h2; BsL[row][cc + 2] = tf32r(v.z - h2);
            BsH[row][cc + 3] = h3; BsL[row][cc + 3] = tf32r(v.w - h3);
        }
        __syncthreads();

#pragma unroll
        for (int kk = 0; kk < BK; kk += 8) {
            const int rA = warp * 16 + g;
            uint32_t ah0 = __float_as_uint(AsH[rA][kk + t]);
            uint32_t ah1 = __float_as_uint(AsH[rA + 8][kk + t]);
            uint32_t ah2 = __float_as_uint(AsH[rA][kk + t + 4]);
            uint32_t ah3 = __float_as_uint(AsH[rA + 8][kk + t + 4]);
            uint32_t al0 = __float_as_uint(AsL[rA][kk + t]);
            uint32_t al1 = __float_as_uint(AsL[rA + 8][kk + t]);
            uint32_t al2 = __float_as_uint(AsL[rA][kk + t + 4]);
            uint32_t al3 = __float_as_uint(AsL[rA + 8][kk + t + 4]);
#pragma unroll
            for (int nt = 0; nt < 8; nt++) {
                uint32_t bh0 = __float_as_uint(BsH[kk + t][nt * 8 + g]);
                uint32_t bh1 = __float_as_uint(BsH[kk + t + 4][nt * 8 + g]);
                uint32_t bl0 = __float_as_uint(BsL[kk + t][nt * 8 + g]);
                uint32_t bl1 = __float_as_uint(BsL[kk + t + 4][nt * 8 + g]);
                MMA8(acc[nt], ah0, ah1, ah2, ah3, bh0, bh1);
                MMA8(acc[nt], al0, al1, al2, al3, bh0, bh1);
                MMA8(acc[nt], ah0, ah1, ah2, ah3, bl0, bl1);
            }
        }
        __syncthreads();
    }

    // ---------------- epilogue ----------------
    // thread holds rows {rowlo, rowhi}, cols nt*8 + t*2 + {0,1}
    const int rowlo = r0 + warp * 16 + g;
    const int rowhi = rowlo + 8;

    float av[8][2], dv[8][2];
#pragma unroll
    for (int nt = 0; nt < 8; nt++)
#pragma unroll
        for (int j = 0; j < 2; j++) {
            int col = nt * 8 + t * 2 + j;
            av[nt][j] = att_s[c0 + col];
            dv[nt][j] = att_d[c0 + col];
        }

    float pslo = 0.f, pdlo = 0.f, pshi = 0.f, pdhi = 0.f;
#pragma unroll
    for (int nt = 0; nt < 8; nt++) {
        pslo = fmaf(acc[nt][0], av[nt][0], fmaf(acc[nt][1], av[nt][1], pslo));
        pdlo = fmaf(acc[nt][0], dv[nt][0], fmaf(acc[nt][1], dv[nt][1], pdlo));
        pshi = fmaf(acc[nt][2], av[nt][0], fmaf(acc[nt][3], av[nt][1], pshi));
        pdhi = fmaf(acc[nt][2], dv[nt][0], fmaf(acc[nt][3], dv[nt][1], pdhi));
    }

    if (rowlo < N_NODES) {
#pragma unroll
        for (int nt = 0; nt < 8; nt++)
            *(float2*)&g_h[rowlo * HF + c0 + nt * 8 + t * 2] =
                make_float2(acc[nt][0], acc[nt][1]);
    }
    if (rowhi < N_NODES) {
#pragma unroll
        for (int nt = 0; nt < 8; nt++)
            *(float2*)&g_h[rowhi * HF + c0 + nt * 8 + t * 2] =
                make_float2(acc[nt][2], acc[nt][3]);
    }

    // reduce over the 4 quad lanes (same g, t=0..3)
#pragma unroll
    for (int o = 1; o <= 2; o <<= 1) {
        pslo += __shfl_xor_sync(0xffffffffu, pslo, o);
        pdlo += __shfl_xor_sync(0xffffffffu, pdlo, o);
        pshi += __shfl_xor_sync(0xffffffffu, pshi, o);
        pdhi += __shfl_xor_sync(0xffffffffu, pdhi, o);
    }

    if (t == 0) {
        if (rowlo < N_NODES) {
            int i = rowlo * HEADS + head;
            g_asrc[i] = pslo;
            g_adst[i] = pdlo;
            float ex = expf(leaky(pslo + pdlo));
            g_exself[i] = ex;
            g_denom[i] = ex;
        }
        if (rowhi < N_NODES) {
            int i = rowhi * HEADS + head;
            g_asrc[i] = pshi;
            g_adst[i] = pdhi;
            float ex = expf(leaky(pshi + pdhi));
            g_exself[i] = ex;
            g_denom[i] = ex;
        }
    }
}

// ---------------------------------------------------------------------------
// K3: per edge: numerators, accumulate denominators (edge_index is INT32)
// ---------------------------------------------------------------------------
__global__ void k_edge_exp(const int* __restrict__ ei)
{
    int e = blockIdx.x * blockDim.x + threadIdx.x;
    if (e >= N_EDGES) return;
    int s = ei[e];
    int d = ei[N_EDGES + e];
    float4 as = *(const float4*)&g_asrc[s * HEADS];
    float4 ad = *(const float4*)&g_adst[d * HEADS];
    float4 ex;
    ex.x = expf(leaky(as.x + ad.x));
    ex.y = expf(leaky(as.y + ad.y));
    ex.z = expf(leaky(as.z + ad.z));
    ex.w = expf(leaky(as.w + ad.w));
    *(float4*)&g_ex[e * HEADS] = ex;
    atomicAdd(&g_denom[d * HEADS + 0], ex.x);
    atomicAdd(&g_denom[d * HEADS + 1], ex.y);
    atomicAdd(&g_denom[d * HEADS + 2], ex.z);
    atomicAdd(&g_denom[d * HEADS + 3], ex.w);
}

// ---------------------------------------------------------------------------
// K4: init output with self-loop message + bias (fully overwrites d_out)
// ---------------------------------------------------------------------------
__global__ void k_out_init(float* __restrict__ out, const float* __restrict__ bias)
{
    int t = blockIdx.x * blockDim.x + threadIdx.x;   // float4 index
    if (t >= N_NODES * (HF / 4)) return;
    int node = t >> 6;
    int c4 = t & 63;              // float4 column
    int head = c4 >> 4;
    float alpha = g_exself[node * HEADS + head] / g_denom[node * HEADS + head];
    float4 h = *(const float4*)&g_h[node * HF + c4 * 4];
    float4 b = *(const float4*)&bias[c4 * 4];
    float4 o;
    o.x = fmaf(h.x, alpha, b.x);
    o.y = fmaf(h.y, alpha, b.y);
    o.z = fmaf(h.z, alpha, b.z);
    o.w = fmaf(h.w, alpha, b.w);
    ((float4*)out)[t] = o;
}

// ---------------------------------------------------------------------------
// K5: aggregation. one warp per edge; 256 floats = 2 float4 per lane.
//     vector reductions (red.global.add.v4.f32), no return trip.
// ---------------------------------------------------------------------------
__global__ __launch_bounds__(256) void k_agg(const int* __restrict__ ei,
                                             float* __restrict__ out)
{
    int w = (blockIdx.x * blockDim.x + threadIdx.x) >> 5;
    if (w >= N_EDGES) return;
    int lane = threadIdx.x & 31;
    int s = ei[w];
    int d = ei[N_EDGES + w];

    int h0 = lane >> 4;           // head for cols [lane*4, lane*4+3]  (0 or 1)
    int h1 = h0 + 2;              // head for cols 128 + lane*4

    float al0 = g_ex[w * HEADS + h0] / g_denom[d * HEADS + h0];
    float al1 = g_ex[w * HEADS + h1] / g_denom[d * HEADS + h1];

    const float4* hs = (const float4*)&g_h[s * HF];
    float* ob = out + d * HF;

    float4 v0 = hs[lane];
    float4 v1 = hs[32 + lane];

    red_add_v4(&ob[lane * 4],       v0.x * al0, v0.y * al0, v0.z * al0, v0.w * al0);
    red_add_v4(&ob[128 + lane * 4], v1.x * al1, v1.y * al1, v1.z * al1, v1.w * al1);
}

// ---------------------------------------------------------------------------
extern "C" void kernel_launch(void* const* d_in, const int* in_sizes, int n_in,
                              void* d_out, int out_size)
{
    const float* x     = (const float*)d_in[0];
    const int*   ei    = (const int*)d_in[1];     // int32! (JAX x64 disabled)
    const float* W     = (const float*)d_in[2];
    const float* att_s = (const float*)d_in[3];
    const float* att_d = (const float*)d_in[4];
    const float* bias  = (const float*)d_in[5];
    float*       out   = (float*)d_out;

    // K1: tensor-core projection + fused attention halves + self-loop init
    dim3 g1((N_NODES + 127) / 128, HEADS);
    k_gemm_tc<<<g1, 256>>>(x, W, att_s, att_d);

    // K3: edge numerators + denom accumulation
    k_edge_exp<<<(N_EDGES + 255) / 256, 256>>>(ei);

    // K4: output init (self-loop message + bias)
    k_out_init<<<(N_NODES * (HF / 4) + 255) / 256, 256>>>(out, bias);

    // K5: weighted aggregation (warp per edge)
    k_agg<<<(N_EDGES * 32 + 255) / 256, 256>>>(ei, out);
}

// round 4
// speedup vs baseline: 1.1976x; 1.1976x over previous
#include <cuda_runtime.h>
#include <cstdint>

#define N_NODES 50000
#define N_EDGES 800000
#define IN_F    256
#define HEADS   4
#define OUTF    64
#define HF      256   // HEADS*OUTF
#define SLOPE   0.2f

// ---------------- scratch (device globals; no allocation allowed) ----------
__device__ __align__(16) float g_h[N_NODES * HF];        // 51.2 MB projected features
__device__ __align__(16) float g_asrc[N_NODES * HEADS];
__device__ __align__(16) float g_adst[N_NODES * HEADS];
__device__ __align__(16) float g_exself[N_NODES * HEADS];
__device__ int   g_cnt[N_NODES];                          // in-degree histogram
__device__ int   g_off[N_NODES + 1];                      // CSR offsets
__device__ int   g_cur[N_NODES];                          // scatter cursors
__device__ int   g_srt_src[N_EDGES];                      // dst-sorted src ids
__device__ __align__(16) float g_srt_ex[N_EDGES * HEADS]; // dst-sorted edge numerators

__device__ __forceinline__ float leaky(float v) {
    return v > 0.0f ? v : SLOPE * v;
}

// ---------------------------------------------------------------------------
// K1: h = x @ W (SIMT tiled fp32; BM=128,BN=64==one head,BK=32).
//     Epilogue fuses a_src/a_dst head-dot + self-loop exp.
// ---------------------------------------------------------------------------
#define BM 128
#define BN 64
#define BK 32
#define TM 8
#define TN 4

__global__ __launch_bounds__(256) void k_gemm(const float* __restrict__ x,
                                              const float* __restrict__ W,
                                              const float* __restrict__ att_s,
                                              const float* __restrict__ att_d)
{
    __shared__ float As[BK][BM + 1];
    __shared__ float Bs[BK][BN];

    const int head = blockIdx.y;
    const int r0 = blockIdx.x * BM;
    const int c0 = head * OUTF;
    const int tid = threadIdx.x;
    const int tx = tid & 15;
    const int ty = tid >> 4;

    float acc[TM][TN];
#pragma unroll
    for (int i = 0; i < TM; i++)
#pragma unroll
        for (int j = 0; j < TN; j++) acc[i][j] = 0.0f;

    for (int k0 = 0; k0 < IN_F; k0 += BK) {
#pragma unroll
        for (int i = 0; i < 4; i++) {
            int q = tid + i * 256;
            int row = q >> 3;
            int cc = (q & 7) << 2;
            int r = r0 + row;
            float4 v = make_float4(0.f, 0.f, 0.f, 0.f);
            if (r < N_NODES) v = *(const float4*)&x[r * IN_F + k0 + cc];
            As[cc + 0][row] = v.x;
            As[cc + 1][row] = v.y;
            As[cc + 2][row] = v.z;
            As[cc + 3][row] = v.w;
        }
#pragma unroll
        for (int i = 0; i < 2; i++) {
            int q = tid + i * 256;
            int row = q >> 4;
            int cc = (q & 15) << 2;
            *(float4*)&Bs[row][cc] = *(const float4*)&W[(k0 + row) * HF + c0 + cc];
        }
        __syncthreads();

#pragma unroll
        for (int k = 0; k < BK; k++) {
            float a[TM];
#pragma unroll
            for (int i = 0; i < TM; i++) a[i] = As[k][ty * TM + i];
            float4 b = *(float4*)&Bs[k][tx * TN];
#pragma unroll
            for (int i = 0; i < TM; i++) {
                acc[i][0] = fmaf(a[i], b.x, acc[i][0]);
                acc[i][1] = fmaf(a[i], b.y, acc[i][1]);
                acc[i][2] = fmaf(a[i], b.z, acc[i][2]);
                acc[i][3] = fmaf(a[i], b.w, acc[i][3]);
            }
        }
        __syncthreads();
    }

    float av[TN], dv[TN];
#pragma unroll
    for (int j = 0; j < TN; j++) {
        av[j] = att_s[c0 + tx * TN + j];
        dv[j] = att_d[c0 + tx * TN + j];
    }

#pragma unroll
    for (int i = 0; i < TM; i++) {
        int m = r0 + ty * TM + i;
        bool ok = (m < N_NODES);
        if (ok) {
            float4 hv = make_float4(acc[i][0], acc[i][1], acc[i][2], acc[i][3]);
            *(float4*)&g_h[m * HF + c0 + tx * TN] = hv;
        }
        float ps = 0.f, pd = 0.f;
#pragma unroll
        for (int j = 0; j < TN; j++) {
            ps = fmaf(acc[i][j], av[j], ps);
            pd = fmaf(acc[i][j], dv[j], pd);
        }
#pragma unroll
        for (int o = 8; o > 0; o >>= 1) {
            ps += __shfl_xor_sync(0xffffffffu, ps, o);
            pd += __shfl_xor_sync(0xffffffffu, pd, o);
        }
        if (tx == 0 && ok) {
            int idx = m * HEADS + head;
            g_asrc[idx] = ps;
            g_adst[idx] = pd;
            g_exself[idx] = expf(leaky(ps + pd));   // self-loop numerator
        }
    }
}

// ---------------------------------------------------------------------------
// K2a: zero histogram
// ---------------------------------------------------------------------------
__global__ void k_zero()
{
    int i = blockIdx.x * blockDim.x + threadIdx.x;
    if (i < N_NODES) g_cnt[i] = 0;
}

// ---------------------------------------------------------------------------
// K2b: in-degree histogram over dst
// ---------------------------------------------------------------------------
__global__ void k_hist(const int* __restrict__ ei)
{
    int e = blockIdx.x * blockDim.x + threadIdx.x;
    if (e >= N_EDGES) return;
    atomicAdd(&g_cnt[ei[N_EDGES + e]], 1);
}

// ---------------------------------------------------------------------------
// K2c: single-block exclusive scan -> g_off, g_cur
// ---------------------------------------------------------------------------
#define SCAN_T 1024
__global__ __launch_bounds__(SCAN_T) void k_scan()
{
    __shared__ int sums[SCAN_T];
    const int tid = threadIdx.x;
    const int chunk = (N_NODES + SCAN_T - 1) / SCAN_T;   // 49
    const int b = tid * chunk;
    const int e = min(b + chunk, N_NODES);

    int s = 0;
    for (int i = b; i < e; i++) s += g_cnt[i];
    sums[tid] = s;
    __syncthreads();

    for (int off = 1; off < SCAN_T; off <<= 1) {
        int v = 0;
        if (tid >= off) v = sums[tid - off];
        __syncthreads();
        if (tid >= off) sums[tid] += v;
        __syncthreads();
    }

    int run = (tid > 0) ? sums[tid - 1] : 0;   // exclusive base
    for (int i = b; i < e; i++) {
        int c = g_cnt[i];
        g_off[i] = run;
        g_cur[i] = run;
        run += c;
    }
    if (tid == SCAN_T - 1) g_off[N_NODES] = run;
}

// ---------------------------------------------------------------------------
// K2d: scatter edges into dst-sorted order; compute edge numerators here
// ---------------------------------------------------------------------------
__global__ void k_scatter(const int* __restrict__ ei)
{
    int e = blockIdx.x * blockDim.x + threadIdx.x;
    if (e >= N_EDGES) return;
    int s = ei[e];
    int d = ei[N_EDGES + e];
    float4 as = *(const float4*)&g_asrc[s * HEADS];
    float4 ad = *(const float4*)&g_adst[d * HEADS];
    float4 ex;
    ex.x = expf(leaky(as.x + ad.x));
    ex.y = expf(leaky(as.y + ad.y));
    ex.z = expf(leaky(as.z + ad.z));
    ex.w = expf(leaky(as.w + ad.w));
    int pos = atomicAdd(&g_cur[d], 1);
    g_srt_src[pos] = s;
    *(float4*)&g_srt_ex[pos * HEADS] = ex;
}

// ---------------------------------------------------------------------------
// K3: gather-aggregate. One warp per destination node. No atomics.
//     Lane owns cols [lane*4, lane*4+3] (head h0) and [128+lane*4 ...] (h1).
//     Accumulates weighted sums AND per-head denominators, then divides
//     once and writes the final output with bias.
// ---------------------------------------------------------------------------
__global__ __launch_bounds__(256) void k_agg(float* __restrict__ out,
                                             const float* __restrict__ bias)
{
    int d = (blockIdx.x * blockDim.x + threadIdx.x) >> 5;
    if (d >= N_NODES) return;
    const int lane = threadIdx.x & 31;
    const int h0 = lane >> 4;        // 0 or 1
    const int h1 = h0 + 2;           // 2 or 3

    const int beg = g_off[d];
    const int end = g_off[d + 1];

    float4 acc0 = make_float4(0.f, 0.f, 0.f, 0.f);
    float4 acc1 = make_float4(0.f, 0.f, 0.f, 0.f);
    float den0 = 0.f, den1 = 0.f;

    for (int p = beg; p < end; p++) {
        int s = g_srt_src[p];                       // broadcast load
        float e0 = g_srt_ex[p * HEADS + h0];
        float e1 = g_srt_ex[p * HEADS + h1];
        const float4* hs = (const float4*)&g_h[s * HF];
        float4 v0 = hs[lane];
        float4 v1 = hs[32 + lane];
        acc0.x = fmaf(e0, v0.x, acc0.x);
        acc0.y = fmaf(e0, v0.y, acc0.y);
        acc0.z = fmaf(e0, v0.z, acc0.z);
        acc0.w = fmaf(e0, v0.w, acc0.w);
        acc1.x = fmaf(e1, v1.x, acc1.x);
        acc1.y = fmaf(e1, v1.y, acc1.y);
        acc1.z = fmaf(e1, v1.z, acc1.z);
        acc1.w = fmaf(e1, v1.w, acc1.w);
        den0 += e0;
        den1 += e1;
    }

    // self-loop
    {
        float e0 = g_exself[d * HEADS + h0];
        float e1 = g_exself[d * HEADS + h1];
        const float4* hd = (const float4*)&g_h[d * HF];
        float4 v0 = hd[lane];
        float4 v1 = hd[32 + lane];
        acc0.x = fmaf(e0, v0.x, acc0.x);
        acc0.y = fmaf(e0, v0.y, acc0.y);
        acc0.z = fmaf(e0, v0.z, acc0.z);
        acc0.w = fmaf(e0, v0.w, acc0.w);
        acc1.x = fmaf(e1, v1.x, acc1.x);
        acc1.y = fmaf(e1, v1.y, acc1.y);
        acc1.z = fmaf(e1, v1.z, acc1.z);
        acc1.w = fmaf(e1, v1.w, acc1.w);
        den0 += e0;
        den1 += e1;
    }

    float inv0 = 1.0f / den0;
    float inv1 = 1.0f / den1;
    float4 b0 = *(const float4*)&bias[lane * 4];
    float4 b1 = *(const float4*)&bias[128 + lane * 4];
    float4 o0, o1;
    o0.x = fmaf(acc0.x, inv0, b0.x);
    o0.y = fmaf(acc0.y, inv0, b0.y);
    o0.z = fmaf(acc0.z, inv0, b0.z);
    o0.w = fmaf(acc0.w, inv0, b0.w);
    o1.x = fmaf(acc1.x, inv1, b1.x);
    o1.y = fmaf(acc1.y, inv1, b1.y);
    o1.z = fmaf(acc1.z, inv1, b1.z);
    o1.w = fmaf(acc1.w, inv1, b1.w);

    float4* ob = (float4*)&out[d * HF];
    ob[lane] = o0;
    ob[32 + lane] = o1;
}

// ---------------------------------------------------------------------------
extern "C" void kernel_launch(void* const* d_in, const int* in_sizes, int n_in,
                              void* d_out, int out_size)
{
    const float* x     = (const float*)d_in[0];
    const int*   ei    = (const int*)d_in[1];     // int32 (JAX x64 disabled)
    const float* W     = (const float*)d_in[2];
    const float* att_s = (const float*)d_in[3];
    const float* att_d = (const float*)d_in[4];
    const float* bias  = (const float*)d_in[5];
    float*       out   = (float*)d_out;

    // K1: projection + fused attention halves + self-loop numerator
    dim3 g1((N_NODES + BM - 1) / BM, HEADS);
    k_gemm<<<g1, 256>>>(x, W, att_s, att_d);

    // CSR build (independent of GEMM except scatter needs a_src/a_dst)
    k_zero<<<(N_NODES + 255) / 256, 256>>>();
    k_hist<<<(N_EDGES + 255) / 256, 256>>>(ei);
    k_scan<<<1, SCAN_T>>>();
    k_scatter<<<(N_EDGES + 255) / 256, 256>>>(ei);

    // K3: gather aggregation, final output (bias fused)
    k_agg<<<(N_NODES * 32 + 255) / 256, 256>>>(out, bias);
}

// round 5
// speedup vs baseline: 1.5366x; 1.2830x over previous
#include <cuda_runtime.h>
#include <cstdint>

#define N_NODES 50000
#define N_EDGES 800000
#define IN_F    256
#define HEADS   4
#define OUTF    64
#define HF      256   // HEADS*OUTF
#define SLOPE   0.2f

// ---------------- scratch (device globals; no allocation allowed) ----------
__device__ __align__(16) float g_h[N_NODES * HF];        // 51.2 MB projected features
__device__ __align__(16) float g_asrc[N_NODES * HEADS];
__device__ __align__(16) float g_adst[N_NODES * HEADS];
__device__ __align__(16) float g_exself[N_NODES * HEADS];
__device__ int   g_cnt[N_NODES];                          // in-degree histogram
__device__ int   g_off[N_NODES + 1];                      // CSR offsets
__device__ int   g_cur[N_NODES];                          // scatter cursors
__device__ int   g_bsum[256];                             // per-block chunk sums
__device__ int   g_bbase[256];                            // per-block exclusive bases
__device__ int   g_srt_src[N_EDGES];                      // dst-sorted src ids
__device__ __align__(16) float g_srt_ex[N_EDGES * HEADS]; // dst-sorted edge numerators

#define SBLK 256
#define NSB  ((N_NODES + SBLK - 1) / SBLK)   // 196 scan blocks

__device__ __forceinline__ float leaky(float v) {
    return v > 0.0f ? v : SLOPE * v;
}

// ---------------------------------------------------------------------------
// K1: h = x @ W (SIMT tiled fp32; BM=128,BN=64==one head,BK=32).
//     Epilogue fuses a_src/a_dst head-dot + self-loop exp.
// ---------------------------------------------------------------------------
#define BM 128
#define BN 64
#define BK 32
#define TM 8
#define TN 4

__global__ __launch_bounds__(256) void k_gemm(const float* __restrict__ x,
                                              const float* __restrict__ W,
                                              const float* __restrict__ att_s,
                                              const float* __restrict__ att_d)
{
    __shared__ float As[BK][BM + 1];
    __shared__ float Bs[BK][BN];

    const int head = blockIdx.y;
    const int r0 = blockIdx.x * BM;
    const int c0 = head * OUTF;
    const int tid = threadIdx.x;
    const int tx = tid & 15;
    const int ty = tid >> 4;

    float acc[TM][TN];
#pragma unroll
    for (int i = 0; i < TM; i++)
#pragma unroll
        for (int j = 0; j < TN; j++) acc[i][j] = 0.0f;

    for (int k0 = 0; k0 < IN_F; k0 += BK) {
#pragma unroll
        for (int i = 0; i < 4; i++) {
            int q = tid + i * 256;
            int row = q >> 3;
            int cc = (q & 7) << 2;
            int r = r0 + row;
            float4 v = make_float4(0.f, 0.f, 0.f, 0.f);
            if (r < N_NODES) v = *(const float4*)&x[r * IN_F + k0 + cc];
            As[cc + 0][row] = v.x;
            As[cc + 1][row] = v.y;
            As[cc + 2][row] = v.z;
            As[cc + 3][row] = v.w;
        }
#pragma unroll
        for (int i = 0; i < 2; i++) {
            int q = tid + i * 256;
            int row = q >> 4;
            int cc = (q & 15) << 2;
            *(float4*)&Bs[row][cc] = *(const float4*)&W[(k0 + row) * HF + c0 + cc];
        }
        __syncthreads();

#pragma unroll
        for (int k = 0; k < BK; k++) {
            float a[TM];
#pragma unroll
            for (int i = 0; i < TM; i++) a[i] = As[k][ty * TM + i];
            float4 b = *(float4*)&Bs[k][tx * TN];
#pragma unroll
            for (int i = 0; i < TM; i++) {
                acc[i][0] = fmaf(a[i], b.x, acc[i][0]);
                acc[i][1] = fmaf(a[i], b.y, acc[i][1]);
                acc[i][2] = fmaf(a[i], b.z, acc[i][2]);
                acc[i][3] = fmaf(a[i], b.w, acc[i][3]);
            }
        }
        __syncthreads();
    }

    float av[TN], dv[TN];
#pragma unroll
    for (int j = 0; j < TN; j++) {
        av[j] = att_s[c0 + tx * TN + j];
        dv[j] = att_d[c0 + tx * TN + j];
    }

#pragma unroll
    for (int i = 0; i < TM; i++) {
        int m = r0 + ty * TM + i;
        bool ok = (m < N_NODES);
        if (ok) {
            float4 hv = make_float4(acc[i][0], acc[i][1], acc[i][2], acc[i][3]);
            *(float4*)&g_h[m * HF + c0 + tx * TN] = hv;
        }
        float ps = 0.f, pd = 0.f;
#pragma unroll
        for (int j = 0; j < TN; j++) {
            ps = fmaf(acc[i][j], av[j], ps);
            pd = fmaf(acc[i][j], dv[j], pd);
        }
#pragma unroll
        for (int o = 8; o > 0; o >>= 1) {
            ps += __shfl_xor_sync(0xffffffffu, ps, o);
            pd += __shfl_xor_sync(0xffffffffu, pd, o);
        }
        if (tx == 0 && ok) {
            int idx = m * HEADS + head;
            g_asrc[idx] = ps;
            g_adst[idx] = pd;
            g_exself[idx] = expf(leaky(ps + pd));   // self-loop numerator
        }
    }
}

// ---------------------------------------------------------------------------
// K2a: zero histogram
// ---------------------------------------------------------------------------
__global__ void k_zero()
{
    int i = blockIdx.x * blockDim.x + threadIdx.x;
    if (i < N_NODES) g_cnt[i] = 0;
}

// ---------------------------------------------------------------------------
// K2b: in-degree histogram over dst
// ---------------------------------------------------------------------------
__global__ void k_hist(const int* __restrict__ ei)
{
    int e = blockIdx.x * blockDim.x + threadIdx.x;
    if (e >= N_EDGES) return;
    atomicAdd(&g_cnt[ei[N_EDGES + e]], 1);
}

// ---------------------------------------------------------------------------
// K2c: 3-stage chip-wide exclusive scan of g_cnt -> g_off, g_cur
// ---------------------------------------------------------------------------
__global__ __launch_bounds__(SBLK) void k_blocksum()
{
    __shared__ int red[SBLK / 32];
    int i = blockIdx.x * SBLK + threadIdx.x;
    int c = (i < N_NODES) ? g_cnt[i] : 0;
    int v = c;
#pragma unroll
    for (int o = 16; o > 0; o >>= 1) v += __shfl_xor_sync(0xffffffffu, v, o);
    if ((threadIdx.x & 31) == 0) red[threadIdx.x >> 5] = v;
    __syncthreads();
    if (threadIdx.x < SBLK / 32) {
        int w = red[threadIdx.x];
#pragma unroll
        for (int o = SBLK / 64; o > 0; o >>= 1) w += __shfl_xor_sync(0xffffffffu, w, o);
        if (threadIdx.x == 0) g_bsum[blockIdx.x] = w;
    }
}

__global__ __launch_bounds__(256) void k_scanbsum()
{
    __shared__ int s[256];
    int t = threadIdx.x;
    int v = (t < NSB) ? g_bsum[t] : 0;
    s[t] = v;
    __syncthreads();
#pragma unroll
    for (int off = 1; off < 256; off <<= 1) {
        int u = (t >= off) ? s[t - off] : 0;
        __syncthreads();
        s[t] += u;
        __syncthreads();
    }
    if (t < NSB) g_bbase[t] = s[t] - v;          // exclusive base per block
    if (t == 0) g_off[N_NODES] = N_EDGES;        // total is known statically
}

__global__ __launch_bounds__(SBLK) void k_offsets()
{
    __shared__ int s[SBLK];
    int t = threadIdx.x;
    int i = blockIdx.x * SBLK + t;
    int c = (i < N_NODES) ? g_cnt[i] : 0;
    s[t] = c;
    __syncthreads();
#pragma unroll
    for (int off = 1; off < SBLK; off <<= 1) {
        int u = (t >= off) ? s[t - off] : 0;
        __syncthreads();
        s[t] += u;
        __syncthreads();
    }
    if (i < N_NODES) {
        int o = g_bbase[blockIdx.x] + s[t] - c;  // exclusive
        g_off[i] = o;
        g_cur[i] = o;
    }
}

// ---------------------------------------------------------------------------
// K2d: scatter edges into dst-sorted order; compute edge numerators here
// ---------------------------------------------------------------------------
__global__ void k_scatter(const int* __restrict__ ei)
{
    int e = blockIdx.x * blockDim.x + threadIdx.x;
    if (e >= N_EDGES) return;
    int s = ei[e];
    int d = ei[N_EDGES + e];
    float4 as = *(const float4*)&g_asrc[s * HEADS];
    float4 ad = *(const float4*)&g_adst[d * HEADS];
    float4 ex;
    ex.x = expf(leaky(as.x + ad.x));
    ex.y = expf(leaky(as.y + ad.y));
    ex.z = expf(leaky(as.z + ad.z));
    ex.w = expf(leaky(as.w + ad.w));
    int pos = atomicAdd(&g_cur[d], 1);
    g_srt_src[pos] = s;
    *(float4*)&g_srt_ex[pos * HEADS] = ex;
}

// ---------------------------------------------------------------------------
// K3: gather-aggregate. One warp per destination node. No atomics.
// ---------------------------------------------------------------------------
__global__ __launch_bounds__(256) void k_agg(float* __restrict__ out,
                                             const float* __restrict__ bias)
{
    int d = (blockIdx.x * blockDim.x + threadIdx.x) >> 5;
    if (d >= N_NODES) return;
    const int lane = threadIdx.x & 31;
    const int h0 = lane >> 4;        // 0 or 1
    const int h1 = h0 + 2;           // 2 or 3

    const int beg = g_off[d];
    const int end = g_off[d + 1];

    float4 acc0 = make_float4(0.f, 0.f, 0.f, 0.f);
    float4 acc1 = make_float4(0.f, 0.f, 0.f, 0.f);
    float den0 = 0.f, den1 = 0.f;

    for (int p = beg; p < end; p++) {
        int s = g_srt_src[p];                       // broadcast load
        float e0 = g_srt_ex[p * HEADS + h0];
        float e1 = g_srt_ex[p * HEADS + h1];
        const float4* hs = (const float4*)&g_h[s * HF];
        float4 v0 = hs[lane];
        float4 v1 = hs[32 + lane];
        acc0.x = fmaf(e0, v0.x, acc0.x);
        acc0.y = fmaf(e0, v0.y, acc0.y);
        acc0.z = fmaf(e0, v0.z, acc0.z);
        acc0.w = fmaf(e0, v0.w, acc0.w);
        acc1.x = fmaf(e1, v1.x, acc1.x);
        acc1.y = fmaf(e1, v1.y, acc1.y);
        acc1.z = fmaf(e1, v1.z, acc1.z);
        acc1.w = fmaf(e1, v1.w, acc1.w);
        den0 += e0;
        den1 += e1;
    }

    // self-loop
    {
        float e0 = g_exself[d * HEADS + h0];
        float e1 = g_exself[d * HEADS + h1];
        const float4* hd = (const float4*)&g_h[d * HF];
        float4 v0 = hd[lane];
        float4 v1 = hd[32 + lane];
        acc0.x = fmaf(e0, v0.x, acc0.x);
        acc0.y = fmaf(e0, v0.y, acc0.y);
        acc0.z = fmaf(e0, v0.z, acc0.z);
        acc0.w = fmaf(e0, v0.w, acc0.w);
        acc1.x = fmaf(e1, v1.x, acc1.x);
        acc1.y = fmaf(e1, v1.y, acc1.y);
        acc1.z = fmaf(e1, v1.z, acc1.z);
        acc1.w = fmaf(e1, v1.w, acc1.w);
        den0 += e0;
        den1 += e1;
    }

    float inv0 = 1.0f / den0;
    float inv1 = 1.0f / den1;
    float4 b0 = *(const float4*)&bias[lane * 4];
    float4 b1 = *(const float4*)&bias[128 + lane * 4];
    float4 o0, o1;
    o0.x = fmaf(acc0.x, inv0, b0.x);
    o0.y = fmaf(acc0.y, inv0, b0.y);
    o0.z = fmaf(acc0.z, inv0, b0.z);
    o0.w = fmaf(acc0.w, inv0, b0.w);
    o1.x = fmaf(acc1.x, inv1, b1.x);
    o1.y = fmaf(acc1.y, inv1, b1.y);
    o1.z = fmaf(acc1.z, inv1, b1.z);
    o1.w = fmaf(acc1.w, inv1, b1.w);

    float4* ob = (float4*)&out[d * HF];
    ob[lane] = o0;
    ob[32 + lane] = o1;
}

// ---------------------------------------------------------------------------
extern "C" void kernel_launch(void* const* d_in, const int* in_sizes, int n_in,
                              void* d_out, int out_size)
{
    const float* x     = (const float*)d_in[0];
    const int*   ei    = (const int*)d_in[1];     // int32 (JAX x64 disabled)
    const float* W     = (const float*)d_in[2];
    const float* att_s = (const float*)d_in[3];
    const float* att_d = (const float*)d_in[4];
    const float* bias  = (const float*)d_in[5];
    float*       out   = (float*)d_out;

    // K1: projection + fused attention halves + self-loop numerator
    dim3 g1((N_NODES + BM - 1) / BM, HEADS);
    k_gemm<<<g1, 256>>>(x, W, att_s, att_d);

    // CSR build
    k_zero<<<(N_NODES + 255) / 256, 256>>>();
    k_hist<<<(N_EDGES + 255) / 256, 256>>>(ei);
    k_blocksum<<<NSB, SBLK>>>();
    k_scanbsum<<<1, 256>>>();
    k_offsets<<<NSB, SBLK>>>();
    k_scatter<<<(N_EDGES + 255) / 256, 256>>>(ei);

    // K3: gather aggregation, final output (bias fused)
    k_agg<<<(N_NODES * 32 + 255) / 256, 256>>>(out, bias);
}

// round 7
// speedup vs baseline: 1.8166x; 1.1823x over previous
#include <cuda_runtime.h>
#include <cuda_bf16.h>
#include <cstdint>

#define N_NODES 50000
#define N_EDGES 800000
#define IN_F    256
#define HEADS   4
#define OUTF    64
#define HF      256   // HEADS*OUTF
#define SLOPE   0.2f

// ---------------- scratch (device globals; no allocation allowed) ----------
__device__ __align__(16) float g_h[N_NODES * HF];        // 51.2 MB projected features
__device__ __align__(16) float g_asrc[N_NODES * HEADS];
__device__ __align__(16) float g_adst[N_NODES * HEADS];
__device__ __align__(16) float g_exself[N_NODES * HEADS];
__device__ int   g_cnt[N_NODES];                          // in-degree histogram
__device__ int   g_off[N_NODES + 1];                      // CSR offsets
__device__ int   g_cur[N_NODES];                          // scatter cursors
__device__ int   g_bsum[256];                             // per-block chunk sums
__device__ int   g_bbase[256];                            // per-block exclusive bases
__device__ int   g_srt_src[N_EDGES];                      // dst-sorted src ids
__device__ __align__(16) float g_srt_ex[N_EDGES * HEADS]; // dst-sorted edge numerators

#define SBLK 256
#define NSB  ((N_NODES + SBLK - 1) / SBLK)   // 196 scan blocks

__device__ __forceinline__ float leaky(float v) {
    return v > 0.0f ? v : SLOPE * v;
}

__device__ __forceinline__ uint32_t smem_u32(const void* p) {
    return (uint32_t)__cvta_generic_to_shared(p);
}

#define LDSM_X4(d0, d1, d2, d3, addr)                                          \
    asm volatile("ldmatrix.sync.aligned.m8n8.x4.shared.b16 {%0,%1,%2,%3}, [%4];" \
                 : "=r"(d0), "=r"(d1), "=r"(d2), "=r"(d3) : "r"(addr))

#define LDSM_X4T(d0, d1, d2, d3, addr)                                         \
    asm volatile("ldmatrix.sync.aligned.m8n8.x4.trans.shared.b16 {%0,%1,%2,%3}, [%4];" \
                 : "=r"(d0), "=r"(d1), "=r"(d2), "=r"(d3) : "r"(addr))

#define MMA16(c, a0, a1, a2, a3, b0, b1)                                       \
    asm volatile("mma.sync.aligned.m16n8k16.row.col.f32.bf16.bf16.f32 "        \
                 "{%0,%1,%2,%3}, {%4,%5,%6,%7}, {%8,%9}, {%0,%1,%2,%3};"       \
                 : "+f"(c[0]), "+f"(c[1]), "+f"(c[2]), "+f"(c[3])              \
                 : "r"(a0), "r"(a1), "r"(a2), "r"(a3), "r"(b0), "r"(b1))

// ---------------------------------------------------------------------------
// K1: h = x @ W on tensor cores via bf16x3 split (hh + hl + lh; ~1e-5 accuracy)
//     Block tile 128x64 (BN=64 == one head), BK=32. 8 warps, warp tile 16x64.
//     Fragments via ldmatrix (conflict-free padded strides 40 / 72 bf16).
//     Epilogue fuses a_src/a_dst head-dot + self-loop exp.
// ---------------------------------------------------------------------------
#define ASTR 40
#define BSTR 72

__global__ __launch_bounds__(256) void k_gemm_bf16(const float* __restrict__ x,
                                                   const float* __restrict__ W,
                                                   const float* __restrict__ att_s,
                                                   const float* __restrict__ att_d)
{
    __shared__ __nv_bfloat16 Ah[128][ASTR], Al[128][ASTR];
    __shared__ __nv_bfloat16 Bh[32][BSTR], Bl[32][BSTR];

    const int head = blockIdx.y;
    const int r0 = blockIdx.x * 128;
    const int c0 = head * OUTF;
    const int tid = threadIdx.x;
    const int lane = tid & 31;
    const int w = tid >> 5;
    const int g = lane >> 2;      // groupID 0..7
    const int t = lane & 3;       // tid-in-group 0..3
    const int lr = lane & 15;     // ldmatrix row-select
    const int lc = lane >> 4;     // ldmatrix half-select

    float acc[8][4];
#pragma unroll
    for (int i = 0; i < 8; i++)
#pragma unroll
        for (int j = 0; j < 4; j++) acc[i][j] = 0.0f;

    for (int k0 = 0; k0 < IN_F; k0 += 32) {
        // A tile 128x32 fp32 -> bf16 hi/lo (4 float4 per thread)
#pragma unroll
        for (int i = 0; i < 4; i++) {
            int q = tid + i * 256;
            int row = q >> 3;
            int cc = (q & 7) << 2;
            int r = r0 + row;
            float4 v = make_float4(0.f, 0.f, 0.f, 0.f);
            if (r < N_NODES) v = *(const float4*)&x[r * IN_F + k0 + cc];
            float vv[4] = {v.x, v.y, v.z, v.w};
#pragma unroll
            for (int j = 0; j < 4; j++) {
                __nv_bfloat16 h = __float2bfloat16(vv[j]);
                Ah[row][cc + j] = h;
                Al[row][cc + j] = __float2bfloat16(vv[j] - __bfloat162float(h));
            }
        }
        // B tile 32x64 fp32 -> bf16 hi/lo (2 float4 per thread)
#pragma unroll
        for (int i = 0; i < 2; i++) {
            int q = tid + i * 256;
            int row = q >> 4;
            int cc = (q & 15) << 2;
            float4 v = *(const float4*)&W[(k0 + row) * HF + c0 + cc];
            float vv[4] = {v.x, v.y, v.z, v.w};
#pragma unroll
            for (int j = 0; j < 4; j++) {
                __nv_bfloat16 h = __float2bfloat16(vv[j]);
                Bh[row][cc + j] = h;
                Bl[row][cc + j] = __float2bfloat16(vv[j] - __bfloat162float(h));
            }
        }
        __syncthreads();

#pragma unroll
        for (int kk = 0; kk < 32; kk += 16) {
            uint32_t ah[4], al[4];
            LDSM_X4(ah[0], ah[1], ah[2], ah[3],
                    smem_u32(&Ah[w * 16 + lr][kk + lc * 8]));
            LDSM_X4(al[0], al[1], al[2], al[3],
                    smem_u32(&Al[w * 16 + lr][kk + lc * 8]));
#pragma unroll
            for (int nn = 0; nn < 4; nn++) {
                uint32_t bh[4], bl[4];
                LDSM_X4T(bh[0], bh[1], bh[2], bh[3],
                         smem_u32(&Bh[kk + lr][nn * 16 + lc * 8]));
                LDSM_X4T(bl[0], bl[1], bl[2], bl[3],
                         smem_u32(&Bl[kk + lr][nn * 16 + lc * 8]));
                MMA16(acc[nn * 2],     ah[0], ah[1], ah[2], ah[3], bh[0], bh[1]);
                MMA16(acc[nn * 2],     al[0], al[1], al[2], al[3], bh[0], bh[1]);
                MMA16(acc[nn * 2],     ah[0], ah[1], ah[2], ah[3], bl[0], bl[1]);
                MMA16(acc[nn * 2 + 1], ah[0], ah[1], ah[2], ah[3], bh[2], bh[3]);
                MMA16(acc[nn * 2 + 1], al[0], al[1], al[2], al[3], bh[2], bh[3]);
                MMA16(acc[nn * 2 + 1], ah[0], ah[1], ah[2], ah[3], bl[2], bl[3]);
            }
        }
        __syncthreads();
    }

    // ---------------- epilogue ----------------
    // thread holds rows {rowlo, rowhi}, cols nt*8 + t*2 + {0,1}
    const int rowlo = r0 + w * 16 + g;
    const int rowhi = rowlo + 8;

    float av[8][2], dv[8][2];
#pragma unroll
    for (int nt = 0; nt < 8; nt++)
#pragma unroll
        for (int j = 0; j < 2; j++) {
            int col = nt * 8 + t * 2 + j;
            av[nt][j] = att_s[c0 + col];
            dv[nt][j] = att_d[c0 + col];
        }

    float pslo = 0.f, pdlo = 0.f, pshi = 0.f, pdhi = 0.f;
#pragma unroll
    for (int nt = 0; nt < 8; nt++) {
        pslo = fmaf(acc[nt][0], av[nt][0], fmaf(acc[nt][1], av[nt][1], pslo));
        pdlo = fmaf(acc[nt][0], dv[nt][0], fmaf(acc[nt][1], dv[nt][1], pdlo));
        pshi = fmaf(acc[nt][2], av[nt][0], fmaf(acc[nt][3], av[nt][1], pshi));
        pdhi = fmaf(acc[nt][2], dv[nt][0], fmaf(acc[nt][3], dv[nt][1], pdhi));
    }

    if (rowlo < N_NODES) {
#pragma unroll
        for (int nt = 0; nt < 8; nt++)
            *(float2*)&g_h[rowlo * HF + c0 + nt * 8 + t * 2] =
                make_float2(acc[nt][0], acc[nt][1]);
    }
    if (rowhi < N_NODES) {
#pragma unroll
        for (int nt = 0; nt < 8; nt++)
            *(float2*)&g_h[rowhi * HF + c0 + nt * 8 + t * 2] =
                make_float2(acc[nt][2], acc[nt][3]);
    }

    // reduce over the 4 quad lanes
#pragma unroll
    for (int o = 1; o <= 2; o <<= 1) {
        pslo += __shfl_xor_sync(0xffffffffu, pslo, o);
        pdlo += __shfl_xor_sync(0xffffffffu, pdlo, o);
        pshi += __shfl_xor_sync(0xffffffffu, pshi, o);
        pdhi += __shfl_xor_sync(0xffffffffu, pdhi, o);
    }

    if (t == 0) {
        if (rowlo < N_NODES) {
            int i = rowlo * HEADS + head;
            g_asrc[i] = pslo;
            g_adst[i] = pdlo;
            g_exself[i] = expf(leaky(pslo + pdlo));
        }
        if (rowhi < N_NODES) {
            int i = rowhi * HEADS + head;
            g_asrc[i] = pshi;
            g_adst[i] = pdhi;
            g_exself[i] = expf(leaky(pshi + pdhi));
        }
    }
}

// ---------------------------------------------------------------------------
// K2a: zero histogram
// ---------------------------------------------------------------------------
__global__ void k_zero()
{
    int i = blockIdx.x * blockDim.x + threadIdx.x;
    if (i < N_NODES) g_cnt[i] = 0;
}

// ---------------------------------------------------------------------------
// K2b: in-degree histogram over dst
// ---------------------------------------------------------------------------
__global__ void k_hist(const int* __restrict__ ei)
{
    int e = blockIdx.x * blockDim.x + threadIdx.x;
    if (e >= N_EDGES) return;
    atomicAdd(&g_cnt[ei[N_EDGES + e]], 1);
}

// ---------------------------------------------------------------------------
// K2c: 3-stage chip-wide exclusive scan of g_cnt -> g_off, g_cur
// ---------------------------------------------------------------------------
__global__ __launch_bounds__(SBLK) void k_blocksum()
{
    __shared__ int red[SBLK / 32];
    int i = blockIdx.x * SBLK + threadIdx.x;
    int c = (i < N_NODES) ? g_cnt[i] : 0;
    int v = c;
#pragma unroll
    for (int o = 16; o > 0; o >>= 1) v += __shfl_xor_sync(0xffffffffu, v, o);
    if ((threadIdx.x & 31) == 0) red[threadIdx.x >> 5] = v;
    __syncthreads();
    if (threadIdx.x < SBLK / 32) {
        int w = red[threadIdx.x];
#pragma unroll
        for (int o = SBLK / 64; o > 0; o >>= 1) w += __shfl_xor_sync(0xffffffffu, w, o);
        if (threadIdx.x == 0) g_bsum[blockIdx.x] = w;
    }
}

__global__ __launch_bounds__(256) void k_scanbsum()
{
    __shared__ int s[256];
    int t = threadIdx.x;
    int v = (t < NSB) ? g_bsum[t] : 0;
    s[t] = v;
    __syncthreads();
#pragma unroll
    for (int off = 1; off < 256; off <<= 1) {
        int u = (t >= off) ? s[t - off] : 0;
        __syncthreads();
        s[t] += u;
        __syncthreads();
    }
    if (t < NSB) g_bbase[t] = s[t] - v;
    if (t == 0) g_off[N_NODES] = N_EDGES;
}

__global__ __launch_bounds__(SBLK) void k_offsets()
{
    __shared__ int s[SBLK];
    int t = threadIdx.x;
    int i = blockIdx.x * SBLK + t;
    int c = (i < N_NODES) ? g_cnt[i] : 0;
    s[t] = c;
    __syncthreads();
#pragma unroll
    for (int off = 1; off < SBLK; off <<= 1) {
        int u = (t >= off) ? s[t - off] : 0;
        __syncthreads();
        s[t] += u;
        __syncthreads();
    }
    if (i < N_NODES) {
        int o = g_bbase[blockIdx.x] + s[t] - c;
        g_off[i] = o;
        g_cur[i] = o;
    }
}

// ---------------------------------------------------------------------------
// K2d: scatter edges into dst-sorted order; compute edge numerators here
// ---------------------------------------------------------------------------
__global__ void k_scatter(const int* __restrict__ ei)
{
    int e = blockIdx.x * blockDim.x + threadIdx.x;
    if (e >= N_EDGES) return;
    int s = ei[e];
    int d = ei[N_EDGES + e];
    float4 as = *(const float4*)&g_asrc[s * HEADS];
    float4 ad = *(const float4*)&g_adst[d * HEADS];
    float4 ex;
    ex.x = expf(leaky(as.x + ad.x));
    ex.y = expf(leaky(as.y + ad.y));
    ex.z = expf(leaky(as.z + ad.z));
    ex.w = expf(leaky(as.w + ad.w));
    int pos = atomicAdd(&g_cur[d], 1);
    g_srt_src[pos] = s;
    *(float4*)&g_srt_ex[pos * HEADS] = ex;
}

// ---------------------------------------------------------------------------
// K3: gather-aggregate. One warp per destination node. No atomics.
// ---------------------------------------------------------------------------
__global__ __launch_bounds__(256) void k_agg(float* __restrict__ out,
                                             const float* __restrict__ bias)
{
    int d = (blockIdx.x * blockDim.x + threadIdx.x) >> 5;
    if (d >= N_NODES) return;
    const int lane = threadIdx.x & 31;
    const int h0 = lane >> 4;        // 0 or 1
    const int h1 = h0 + 2;           // 2 or 3

    const int beg = g_off[d];
    const int end = g_off[d + 1];

    float4 acc0 = make_float4(0.f, 0.f, 0.f, 0.f);
    float4 acc1 = make_float4(0.f, 0.f, 0.f, 0.f);
    float den0 = 0.f, den1 = 0.f;

    for (int p = beg; p < end; p++) {
        int s = g_srt_src[p];
        float e0 = g_srt_ex[p * HEADS + h0];
        float e1 = g_srt_ex[p * HEADS + h1];
        const float4* hs = (const float4*)&g_h[s * HF];
        float4 v0 = hs[lane];
        float4 v1 = hs[32 + lane];
        acc0.x = fmaf(e0, v0.x, acc0.x);
        acc0.y = fmaf(e0, v0.y, acc0.y);
        acc0.z = fmaf(e0, v0.z, acc0.z);
        acc0.w = fmaf(e0, v0.w, acc0.w);
        acc1.x = fmaf(e1, v1.x, acc1.x);
        acc1.y = fmaf(e1, v1.y, acc1.y);
        acc1.z = fmaf(e1, v1.z, acc1.z);
        acc1.w = fmaf(e1, v1.w, acc1.w);
        den0 += e0;
        den1 += e1;
    }

    // self-loop
    {
        float e0 = g_exself[d * HEADS + h0];
        float e1 = g_exself[d * HEADS + h1];
        const float4* hd = (const float4*)&g_h[d * HF];
        float4 v0 = hd[lane];
        float4 v1 = hd[32 + lane];
        acc0.x = fmaf(e0, v0.x, acc0.x);
        acc0.y = fmaf(e0, v0.y, acc0.y);
        acc0.z = fmaf(e0, v0.z, acc0.z);
        acc0.w = fmaf(e0, v0.w, acc0.w);
        acc1.x = fmaf(e1, v1.x, acc1.x);
        acc1.y = fmaf(e1, v1.y, acc1.y);
        acc1.z = fmaf(e1, v1.z, acc1.z);
        acc1.w = fmaf(e1, v1.w, acc1.w);
        den0 += e0;
        den1 += e1;
    }

    float inv0 = 1.0f / den0;
    float inv1 = 1.0f / den1;
    float4 b0 = *(const float4*)&bias[lane * 4];
    float4 b1 = *(const float4*)&bias[128 + lane * 4];
    float4 o0, o1;
    o0.x = fmaf(acc0.x, inv0, b0.x);
    o0.y = fmaf(acc0.y, inv0, b0.y);
    o0.z = fmaf(acc0.z, inv0, b0.z);
    o0.w = fmaf(acc0.w, inv0, b0.w);
    o1.x = fmaf(acc1.x, inv1, b1.x);
    o1.y = fmaf(acc1.y, inv1, b1.y);
    o1.z = fmaf(acc1.z, inv1, b1.z);
    o1.w = fmaf(acc1.w, inv1, b1.w);

    float4* ob = (float4*)&out[d * HF];
    ob[lane] = o0;
    ob[32 + lane] = o1;
}

// ---------------------------------------------------------------------------
extern "C" void kernel_launch(void* const* d_in, const int* in_sizes, int n_in,
                              void* d_out, int out_size)
{
    const float* x     = (const float*)d_in[0];
    const int*   ei    = (const int*)d_in[1];     // int32 (JAX x64 disabled)
    const float* W     = (const float*)d_in[2];
    const float* att_s = (const float*)d_in[3];
    const float* att_d = (const float*)d_in[4];
    const float* bias  = (const float*)d_in[5];
    float*       out   = (float*)d_out;

    // K1: tensor-core projection (bf16x3) + fused attn halves + self-loop
    dim3 g1((N_NODES + 127) / 128, HEADS);
    k_gemm_bf16<<<g1, 256>>>(x, W, att_s, att_d);

    // CSR build
    k_zero<<<(N_NODES + 255) / 256, 256>>>();
    k_hist<<<(N_EDGES + 255) / 256, 256>>>(ei);
    k_blocksum<<<NSB, SBLK>>>();
    k_scanbsum<<<1, 256>>>();
    k_offsets<<<NSB, SBLK>>>();
    k_scatter<<<(N_EDGES + 255) / 256, 256>>>(ei);

    // K3: gather aggregation, final output (bias fused)
    k_agg<<<(N_NODES * 32 + 255) / 256, 256>>>(out, bias);
}